// round 4
// baseline (speedup 1.0000x reference)
#include <cuda_runtime.h>
#include <cuda_bf16.h>
#include <math_constants.h>

// Problem constants (from reference): B=4, S=2048, V=32000, D=8
#define VOCAB   32000
#define SEQLEN  2048
#define NDOM    8

// Scratch accumulators (device globals — no allocation allowed)
__device__ float g_domain_loss[NDOM];
__device__ float g_total_loss;
__device__ float g_mask_count;

// ---------------------------------------------------------------------------
// Kernel 1: zero the scratch accumulators
// ---------------------------------------------------------------------------
__global__ void ce_zero_kernel() {
    int t = threadIdx.x;
    if (t < NDOM) g_domain_loss[t] = 0.0f;
    if (t == NDOM)     g_total_loss = 0.0f;
    if (t == NDOM + 1) g_mask_count = 0.0f;
}

// ---------------------------------------------------------------------------
// Kernel 2: one block per token. Online logsumexp over the 32000-wide row,
// then loss = (m + log s) - logit[label]; accumulate into global scratch.
// ---------------------------------------------------------------------------
__global__ void __launch_bounds__(256, 8)
ce_main_kernel(const float* __restrict__ logits,
               const int* __restrict__ label_ids,      // int64 -> int32 (harness)
               const int* __restrict__ label_mask,     // bool  -> int32 (harness)
               const int* __restrict__ domain_idxs)    // int64 -> int32 (harness)
{
    const int token = blockIdx.x;                       // 0 .. B*S-1
    const float4* __restrict__ row =
        reinterpret_cast<const float4*>(logits + (size_t)token * VOCAB);

    // Per-thread online max/sum
    float m = -CUDART_INF_F;
    float s = 0.0f;

    constexpr int NV4 = VOCAB / 4;                      // 8000
    for (int i = threadIdx.x; i < NV4; i += blockDim.x) {
        float4 v = row[i];
        float mx = fmaxf(fmaxf(v.x, v.y), fmaxf(v.z, v.w));
        if (mx > m) { s *= __expf(m - mx); m = mx; }
        s += __expf(v.x - m) + __expf(v.y - m)
           + __expf(v.z - m) + __expf(v.w - m);
    }

    // Warp reduction of (m, s)
    #pragma unroll
    for (int off = 16; off > 0; off >>= 1) {
        float m2 = __shfl_xor_sync(0xFFFFFFFFu, m, off);
        float s2 = __shfl_xor_sync(0xFFFFFFFFu, s, off);
        float mn = fmaxf(m, m2);
        s = s * __expf(m - mn) + s2 * __expf(m2 - mn);
        m = mn;
    }

    // Cross-warp reduction (identity-padded so the merge is branch-free)
    __shared__ float sm[8];
    __shared__ float ss[8];
    const int warp = threadIdx.x >> 5;
    const int lane = threadIdx.x & 31;
    if (threadIdx.x < 8) { sm[threadIdx.x] = -CUDART_INF_F; ss[threadIdx.x] = 0.0f; }
    __syncthreads();
    if (lane == 0) { sm[warp] = m; ss[warp] = s; }
    __syncthreads();

    if (threadIdx.x == 0) {
        m = sm[0]; s = ss[0];
        #pragma unroll
        for (int i = 1; i < 8; i++) {
            float m2 = sm[i], s2 = ss[i];
            float mn = fmaxf(m, m2);
            s = s * __expf(m - mn) + s2 * __expf(m2 - mn);
            m = mn;
        }

        // Clamp defensively: a wrong assumption should give a finite wrong
        // answer, never an illegal access.
        int lab = label_ids[token];
        lab = min(max(lab, 0), VOCAB - 1);
        const float x_label = __ldg(logits + (size_t)token * VOCAB + (size_t)lab);
        const float loss = (m + __logf(s)) - x_label;   // -log softmax at label

        // Masked-mean numerator / denominator for ce_loss
        if (label_mask[token] != 0) {
            atomicAdd(&g_total_loss, loss);
            atomicAdd(&g_mask_count, 1.0f);
        }
        // Per-domain sums use the UNMASKED per-token loss (matches reference)
        const int b = token / SEQLEN;
        int d = domain_idxs[b];
        d = min(max(d, 0), NDOM - 1);
        atomicAdd(&g_domain_loss[d], loss);
    }
}

// ---------------------------------------------------------------------------
// Kernel 3: finalize. ce = total/count; bincount the (tiny) domain_idxs;
// normalized = domain_loss / (count*S) with empty domains -> 0.
// Output layout (fp32): [ce_loss, normalized[8], samples_per_domain[8]]
// ---------------------------------------------------------------------------
__global__ void ce_finalize_kernel(const int* __restrict__ domain_idxs,
                                   int batch,
                                   float* __restrict__ out,
                                   int out_size)
{
    if (threadIdx.x != 0 || blockIdx.x != 0) return;

    int cnt[NDOM];
    #pragma unroll
    for (int d = 0; d < NDOM; d++) cnt[d] = 0;
    for (int b = 0; b < batch; b++) {
        int d = domain_idxs[b];
        if (d >= 0 && d < NDOM) cnt[d]++;
    }

    const float ce = g_total_loss / g_mask_count;
    if (out_size > 0) out[0] = ce;

    #pragma unroll
    for (int d = 0; d < NDOM; d++) {
        float denom = (float)cnt[d] * (float)SEQLEN;
        float norm  = (denom > 0.0f) ? (g_domain_loss[d] / denom) : 0.0f;
        if (1 + d < out_size)         out[1 + d]         = norm;
        if (1 + NDOM + d < out_size)  out[1 + NDOM + d]  = (float)cnt[d];
    }
}

// ---------------------------------------------------------------------------
// Launch
// ---------------------------------------------------------------------------
extern "C" void kernel_launch(void* const* d_in, const int* in_sizes, int n_in,
                              void* d_out, int out_size)
{
    const float* logits      = (const float*)d_in[0];   // [B,S,V] fp32
    const int*   label_ids   = (const int*)d_in[1];     // [B,S] int32
    const int*   label_mask  = (const int*)d_in[2];     // [B,S] int32 (bool)
    const int*   domain_idxs = (const int*)d_in[3];     // [B] int32

    const int n_tokens = in_sizes[1];      // B*S
    const int batch    = in_sizes[3];      // B

    ce_zero_kernel<<<1, 32>>>();
    ce_main_kernel<<<n_tokens, 256>>>(logits, label_ids, label_mask, domain_idxs);
    ce_finalize_kernel<<<1, 32>>>(domain_idxs, batch, (float*)d_out, out_size);
}

// round 5
// speedup vs baseline: 1.1105x; 1.1105x over previous
#include <cuda_runtime.h>
#include <cuda_bf16.h>
#include <math_constants.h>

// Problem constants (from reference): B=4, S=2048, V=32000, D=8
#define VOCAB   32000
#define SEQLEN  2048
#define NDOM    8

// Scratch accumulators (device globals — zero-initialized at module load;
// the last block resets them after finalizing, so every graph replay sees zeros).
__device__ float        g_domain_loss[NDOM];
__device__ float        g_total_loss;
__device__ float        g_mask_count;
__device__ unsigned int g_done_count;

// ---------------------------------------------------------------------------
// Fused kernel: one block per token.
//  - online logsumexp over the 32000-wide row (streaming __ldcs loads)
//  - loss = (m + log s) - logit[label]; REDG atomics into scratch
//  - last block to finish finalizes the 17 outputs and resets scratch
// ---------------------------------------------------------------------------
__global__ void __launch_bounds__(256, 8)
ce_fused_kernel(const float* __restrict__ logits,
                const int*   __restrict__ label_ids,     // int64 -> int32 (harness)
                const int*   __restrict__ label_mask,    // bool  -> int32 (harness)
                const int*   __restrict__ domain_idxs,   // int64 -> int32 (harness)
                float*       __restrict__ out,
                int out_size, int batch)
{
    const int token = blockIdx.x;                       // 0 .. B*S-1
    const float4* __restrict__ row =
        reinterpret_cast<const float4*>(logits + (size_t)token * VOCAB);

    // Per-thread online max/sum
    float m = -CUDART_INF_F;
    float s = 0.0f;

    constexpr int NV4 = VOCAB / 4;                      // 8000
    for (int i = threadIdx.x; i < NV4; i += blockDim.x) {
        const float4 v = __ldcs(row + i);               // streaming: evict-first
        float mx = fmaxf(fmaxf(v.x, v.y), fmaxf(v.z, v.w));
        if (mx > m) { s *= __expf(m - mx); m = mx; }
        s += __expf(v.x - m) + __expf(v.y - m)
           + __expf(v.z - m) + __expf(v.w - m);
    }

    // Warp reduction of (m, s)
    #pragma unroll
    for (int off = 16; off > 0; off >>= 1) {
        float m2 = __shfl_xor_sync(0xFFFFFFFFu, m, off);
        float s2 = __shfl_xor_sync(0xFFFFFFFFu, s, off);
        float mn = fmaxf(m, m2);
        s = s * __expf(m - mn) + s2 * __expf(m2 - mn);
        m = mn;
    }

    // Cross-warp reduction (identity-padded so the merge is branch-free)
    __shared__ float sm[8];
    __shared__ float ss[8];
    const int warp = threadIdx.x >> 5;
    const int lane = threadIdx.x & 31;
    if (threadIdx.x < 8) { sm[threadIdx.x] = -CUDART_INF_F; ss[threadIdx.x] = 0.0f; }
    __syncthreads();
    if (lane == 0) { sm[warp] = m; ss[warp] = s; }
    __syncthreads();

    if (threadIdx.x == 0) {
        m = sm[0]; s = ss[0];
        #pragma unroll
        for (int i = 1; i < 8; i++) {
            float m2 = sm[i], s2 = ss[i];
            float mn = fmaxf(m, m2);
            s = s * __expf(m - mn) + s2 * __expf(m2 - mn);
            m = mn;
        }

        // Label gather (clamped: wrong assumption -> wrong number, never a fault)
        int lab = label_ids[token];
        lab = min(max(lab, 0), VOCAB - 1);
        const float x_label = __ldg(logits + (size_t)token * VOCAB + (size_t)lab);
        const float loss = (m + __logf(s)) - x_label;   // -log softmax at label

        // Accumulate (fire-and-forget REDG; values ignored)
        if (label_mask[token] != 0) {
            atomicAdd(&g_total_loss, loss);
            atomicAdd(&g_mask_count, 1.0f);
        }
        const int b = token / SEQLEN;
        int d = domain_idxs[b];
        d = min(max(d, 0), NDOM - 1);
        atomicAdd(&g_domain_loss[d], loss);

        // Last-block finalization (threadfence-reduction pattern)
        __threadfence();
        const unsigned int done = atomicAdd(&g_done_count, 1u);
        if (done == gridDim.x - 1) {
            // All other blocks' atomics are visible (fence -> counter chain).
            // Read via L2 (atomics live in L2; L1 was never populated here).
            const float total = __ldcg(&g_total_loss);
            const float cntf  = __ldcg(&g_mask_count);
            float dl[NDOM];
            #pragma unroll
            for (int i = 0; i < NDOM; i++) dl[i] = __ldcg(&g_domain_loss[i]);

            int cnt[NDOM];
            #pragma unroll
            for (int i = 0; i < NDOM; i++) cnt[i] = 0;
            for (int bb = 0; bb < batch; bb++) {
                int dd = domain_idxs[bb];
                if (dd >= 0 && dd < NDOM) cnt[dd]++;
            }

            if (out_size > 0) out[0] = total / fmaxf(cntf, 1.0f);
            #pragma unroll
            for (int i = 0; i < NDOM; i++) {
                float denom = (float)cnt[i] * (float)SEQLEN;
                float norm  = (denom > 0.0f) ? (dl[i] / denom) : 0.0f;
                if (1 + i < out_size)        out[1 + i]        = norm;
                if (1 + NDOM + i < out_size) out[1 + NDOM + i] = (float)cnt[i];
            }

            // Reset scratch for the next graph replay
            #pragma unroll
            for (int i = 0; i < NDOM; i++) g_domain_loss[i] = 0.0f;
            g_total_loss = 0.0f;
            g_mask_count = 0.0f;
            __threadfence();
            g_done_count = 0u;
        }
    }
}

// ---------------------------------------------------------------------------
// Launch: single kernel, graph-capturable, allocation-free
// ---------------------------------------------------------------------------
extern "C" void kernel_launch(void* const* d_in, const int* in_sizes, int n_in,
                              void* d_out, int out_size)
{
    const float* logits      = (const float*)d_in[0];   // [B,S,V] fp32
    const int*   label_ids   = (const int*)d_in[1];     // [B,S] int32
    const int*   label_mask  = (const int*)d_in[2];     // [B,S] int32 (bool)
    const int*   domain_idxs = (const int*)d_in[3];     // [B] int32

    const int n_tokens = in_sizes[1];      // B*S = 8192
    const int batch    = in_sizes[3];      // B = 4

    ce_fused_kernel<<<n_tokens, 256>>>(logits, label_ids, label_mask, domain_idxs,
                                       (float*)d_out, out_size, batch);
}